// round 14
// baseline (speedup 1.0000x reference)
#include <cuda_runtime.h>
#include <cuda_bf16.h>
#include <stdint.h>
#include <stddef.h>
#include <math.h>

#define TT 128
#define BB 32
#define VV 32000
#define EE 512
#define HH 1024
#define KK 1536
#define GG 4096
#define NCHUNK 250       // logits chunks of 128 vocab rows
#define STAGE 20480      // stage bytes: A 16K + B 4K
#define LCH 8            // logits K-chunks of 128 int8
#define GCH 12           // gates K-chunks of 128 int8
#define SP_OFF 24576     // int partial buffer offset in sbuf
#define SMEM_SZ (3 * STAGE)
#define BDIM 8           // steps per launch

// ---------------- scratch ----------------
__device__ __align__(16) float g_h32[32][HH * BB];         // h fp32 [k][b], ring
__device__ __align__(16) signed char g_hq32[32][BB * HH];  // h int8 [b][k], ring
__device__ __align__(16) float g_c[HH * BB];               // c[k][b]
__device__ __align__(16) signed char g_wq[(size_t)VV * HH];
__device__ __align__(16) float g_fsw[VV];
__device__ __align__(16) signed char g_wqg[(size_t)GG * KK];
__device__ __align__(16) float g_sg[GG];
__device__ __align__(16) float g_biasp[GG];
__device__ __align__(16) signed char g_xq[(TT - 1) * BB * EE];
__device__ unsigned g_xmax = 0u;
__device__ float2 g_part[16][NCHUNK * BB];                 // ring by t&15
__device__ float g_loss;
__device__ unsigned g_gcnt[160];                           // per-step gates barrier counters

// ---------------- helpers ----------------
__device__ __forceinline__ uint32_t su32(const void* p) {
    uint32_t a;
    asm("{ .reg .u64 t; cvta.to.shared.u64 t, %1; cvt.u32.u64 %0, t; }" : "=r"(a) : "l"(p));
    return a;
}
#define SWZ(o) ((o) ^ (((o) >> 3) & 0x70))

__device__ __forceinline__ void ldm_x4(uint32_t* r, uint32_t addr) {
    asm volatile("ldmatrix.sync.aligned.m8n8.x4.shared.b16 {%0,%1,%2,%3}, [%4];"
                 : "=r"(r[0]), "=r"(r[1]), "=r"(r[2]), "=r"(r[3]) : "r"(addr));
}
__device__ __forceinline__ void imma16832(int* c, const uint32_t* a, const uint32_t* b) {
    asm volatile("mma.sync.aligned.m16n8k32.row.col.s32.s8.s8.s32 "
                 "{%0,%1,%2,%3}, {%4,%5,%6,%7}, {%8,%9}, {%0,%1,%2,%3};"
                 : "+r"(c[0]), "+r"(c[1]), "+r"(c[2]), "+r"(c[3])
                 : "r"(a[0]), "r"(a[1]), "r"(a[2]), "r"(a[3]), "r"(b[0]), "r"(b[1]));
}
__device__ __forceinline__ void cpa16(uint32_t dst, const void* src) {
    asm volatile("cp.async.cg.shared.global [%0], [%1], 16;" :: "r"(dst), "l"(src) : "memory");
}
#define CPA_COMMIT() asm volatile("cp.async.commit_group;" ::: "memory")
#define CPA_WAIT1()  asm volatile("cp.async.wait_group 1;" ::: "memory")
#define CPA_WAIT0()  asm volatile("cp.async.wait_group 0;" ::: "memory")

__device__ __forceinline__ signed char q8(float v) {
    int x = __float2int_rn(v);
    x = x > 127 ? 127 : (x < -127 ? -127 : x);
    return (signed char)x;
}

// ---------------- setup kernels ----------------
__global__ void k_setup1(const float* __restrict__ W, const float* __restrict__ emb) {
    int wid = blockIdx.x * 8 + (threadIdx.x >> 5);
    int lane = threadIdx.x & 31;
    const float* row = W + (size_t)wid * HH;
    float m = 0.f;
    #pragma unroll
    for (int i = 0; i < 32; i++) m = fmaxf(m, fabsf(row[lane + 32 * i]));
    #pragma unroll
    for (int o = 16; o; o >>= 1) m = fmaxf(m, __shfl_xor_sync(0xFFFFFFFFu, m, o));
    float inv = (m > 1e-30f) ? 127.f / m : 0.f;
    if (lane == 0) g_fsw[wid] = m / (127.f * 127.f);
    signed char* dst = g_wq + (size_t)wid * HH;
    #pragma unroll
    for (int i = 0; i < 32; i++) {
        int k = lane + 32 * i;
        dst[k] = q8(row[k] * inv);
    }
    size_t gtid = (size_t)blockIdx.x * blockDim.x + threadIdx.x;
    size_t n = (size_t)VV * EE, nt = (size_t)gridDim.x * blockDim.x;
    float em = 0.f;
    for (size_t i = gtid; i < n; i += nt) em = fmaxf(em, emb[i]);
    #pragma unroll
    for (int o = 16; o; o >>= 1) em = fmaxf(em, __shfl_xor_sync(0xFFFFFFFFu, em, o));
    if (lane == 0 && em > 0.f) atomicMax(&g_xmax, __float_as_uint(em));
}

__global__ void k_setup2(const float* __restrict__ W_ih, const float* __restrict__ W_hh,
                         const float* __restrict__ b_ih, const float* __restrict__ b_hh) {
    int id = blockIdx.x * 8 + (threadIdx.x >> 5);
    int lane = threadIdx.x & 31;
    int j = id >> 7, r = id & 127;
    int srcrow = (r >> 5) * HH + j * 32 + (r & 31);
    float s_x = __uint_as_float(g_xmax) / 127.f;
    const float sh = 1.f / 127.f;
    float m = 0.f;
    #pragma unroll
    for (int i = 0; i < 48; i++) {
        int k = lane + 32 * i;
        float w = (k < EE) ? W_ih[(size_t)srcrow * EE + k] * s_x
                           : W_hh[(size_t)srcrow * HH + (k - EE)] * sh;
        m = fmaxf(m, fabsf(w));
    }
    #pragma unroll
    for (int o = 16; o; o >>= 1) m = fmaxf(m, __shfl_xor_sync(0xFFFFFFFFu, m, o));
    float inv = (m > 1e-30f) ? 127.f / m : 0.f;
    if (lane == 0) { g_sg[id] = m / 127.f; g_biasp[id] = b_ih[srcrow] + b_hh[srcrow]; }
    signed char* dst = g_wqg + (size_t)id * KK;
    #pragma unroll
    for (int i = 0; i < 48; i++) {
        int k = lane + 32 * i;
        float w = (k < EE) ? W_ih[(size_t)srcrow * EE + k] * s_x
                           : W_hh[(size_t)srcrow * HH + (k - EE)] * sh;
        dst[k] = q8(w * inv);
    }
}

__global__ void k_setup3(const int* __restrict__ indices, const float* __restrict__ emb,
                         const float* __restrict__ h0, const float* __restrict__ c0) {
    if (blockIdx.x < 508) {
        int tb = blockIdx.x * 8 + (threadIdx.x >> 5);
        int lane = threadIdx.x & 31;
        if (tb < (TT - 1) * BB) {
            int idx = indices[tb];
            float inv = 127.f / __uint_as_float(g_xmax);
            const float* e = emb + (size_t)idx * EE;
            signed char* dst = g_xq + (size_t)tb * EE;
            #pragma unroll
            for (int i = 0; i < 16; i++) {
                int k = lane + 32 * i;
                dst[k] = q8(fmaxf(e[k], 0.f) * inv);
            }
        }
    } else {
        int i = (blockIdx.x - 508) * 256 + threadIdx.x;
        if (i < HH * BB) {
            int b = i / HH, k = i % HH;
            g_h32[0][k * BB + b] = h0[i];
            g_c[k * BB + b] = c0[i];
            g_hq32[0][i] = q8(h0[i] * 127.f);
        }
        if (blockIdx.x == 508) {
            if (threadIdx.x < 160) g_gcnt[threadIdx.x] = 0u;
            if (threadIdx.x == 160) g_loss = 0.f;
        }
    }
}

// ---------------- gates (16 warps, K-split x2) + LSTM ----------------
// computes h(s+1): reads hq ring s&31, writes ring (s+1)&31; c is CTA-owned.
__device__ void gates_dev(int s, int jj, char* sbuf) {
    const int tid = threadIdx.x;
    const int w = tid >> 5, lane = tid & 31;
    const int g = w >> 1, kh = w & 1;
    const uint32_t sb = su32(sbuf);
    const char* xqb = (const char*)(g_xq + (size_t)s * BB * EE);
    const char* hqb = (const char*)g_hq32[s & 31];
    const int out = (s + 1) & 31;
    const char* wbase = (const char*)(g_wqg + (size_t)jj * 128 * KK);

    const int ar0 = tid >> 3, ac = tid & 7;
    uint32_t dA0 = SWZ(ar0 * 128 + ac * 16);
    uint32_t dA1 = SWZ((ar0 + 64) * 128 + ac * 16);
    const int brow = (tid & 255) >> 3, bc = tid & 7;
    const uint32_t dB = 16384u + SWZ(brow * 128 + bc * 16);
    const bool bldr = tid < 256;

    #define GISSUE(st, ch) do { \
        uint32_t base = sb + (st) * STAGE; \
        cpa16(base + dA0, wbase + (size_t)ar0 * KK + (ch) * 128 + ac * 16); \
        cpa16(base + dA1, wbase + (size_t)(ar0 + 64) * KK + (ch) * 128 + ac * 16); \
        if (bldr) { \
            const char* bp = ((ch) < 4) ? (xqb + (size_t)brow * EE + (ch) * 128 + bc * 16) \
                                        : (hqb + (size_t)brow * HH + ((ch) - 4) * 128 + bc * 16); \
            cpa16(base + dB, bp); \
        } \
        CPA_COMMIT(); \
    } while (0)

    GISSUE(0, 0);
    GISSUE(1, 1);

    int c[16];
    #pragma unroll
    for (int i = 0; i < 16; i++) c[i] = 0;

    const int lr = lane & 15, lcs = (lane >> 4) << 3;
    const int bn = (lane & 7) + ((lane >> 4) << 3);
    const int bko = ((lane >> 3) & 1) << 3;

    for (int ch = 0; ch < GCH; ch++) {
        if (ch == GCH - 1) CPA_WAIT0(); else CPA_WAIT1();
        __syncthreads();
        if (ch < GCH - 2) GISSUE((ch + 2) % 3, ch + 2);
        uint32_t sA = sb + (ch % 3) * STAGE;
        uint32_t sB = sA + 16384u;
        #pragma unroll
        for (int s4 = 0; s4 < 2; s4++) {
            int ss = kh * 2 + s4;
            uint32_t a[4], b01[4], b23[4];
            ldm_x4(a,   sA + SWZ((g * 16 + lr) * 128 + (ss * 16 + lcs) * 2));
            ldm_x4(b01, sB + SWZ(bn * 128 + (ss * 16 + bko) * 2));
            ldm_x4(b23, sB + SWZ((bn + 16) * 128 + (ss * 16 + bko) * 2));
            imma16832(c + 0,  a, b01 + 0);
            imma16832(c + 4,  a, b01 + 2);
            imma16832(c + 8,  a, b23 + 0);
            imma16832(c + 12, a, b23 + 2);
        }
    }
    #undef GISSUE

    {
        int* sp = (int*)(sbuf + SP_OFF);
        __syncthreads();
        if (kh == 1) {
            #pragma unroll
            for (int i = 0; i < 16; i++) sp[(g * 32 + lane) * 17 + i] = c[i];
        }
        __syncthreads();
        if (kh == 0) {
            #pragma unroll
            for (int i = 0; i < 16; i++) c[i] += sp[(g * 32 + lane) * 17 + i];
        }
    }
    __syncthreads();

    float* sl = (float*)sbuf;   // [128][33]
    if (kh == 0) {
        int r0 = g * 16 + (lane >> 2);
        float s0 = g_sg[jj * 128 + r0],     bb0 = g_biasp[jj * 128 + r0];
        float s1 = g_sg[jj * 128 + r0 + 8], bb1 = g_biasp[jj * 128 + r0 + 8];
        #pragma unroll
        for (int gg = 0; gg < 4; gg++) {
            int col = gg * 8 + 2 * (lane & 3);
            sl[r0 * 33 + col]           = s0 * (float)c[gg * 4 + 0] + bb0;
            sl[r0 * 33 + col + 1]       = s0 * (float)c[gg * 4 + 1] + bb0;
            sl[(r0 + 8) * 33 + col]     = s1 * (float)c[gg * 4 + 2] + bb1;
            sl[(r0 + 8) * 33 + col + 1] = s1 * (float)c[gg * 4 + 3] + bb1;
        }
    }
    __syncthreads();
    {
        int hu = tid >> 4;
        int b0 = (tid & 15) * 2;
        int k = jj * 32 + hu;
        #pragma unroll
        for (int q = 0; q < 2; q++) {
            int b = b0 + q;
            float ig = sl[hu * 33 + b];
            float fg = sl[(32 + hu) * 33 + b];
            float gg = sl[(64 + hu) * 33 + b];
            float og = sl[(96 + hu) * 33 + b];
            float si = 1.f / (1.f + expf(-ig));
            float sf = 1.f / (1.f + expf(-fg));
            float so = 1.f / (1.f + expf(-og));
            float cn = sf * g_c[k * BB + b] + si * tanhf(gg);
            g_c[k * BB + b] = cn;
            float h = so * tanhf(cn);
            g_h32[(s + 1) & 31][k * BB + b] = h;
            g_hq32[out][b * HH + k] = q8(h * 127.f);
        }
    }
}

// ---------------- logits (16 warps: 8 rowgrp x 2 K-split) ----------------
__device__ void logits_dev(const float* __restrict__ b_out, int t, int it, char* sbuf,
                           float (*redM)[32], float (*redS)[32]) {
    const int tid = threadIdx.x;
    const int w = tid >> 5, lane = tid & 31;
    const int g = w >> 1, kh = w & 1;
    const int v0 = it * 128;
    const uint32_t sb = su32(sbuf);
    const char* wbase = (const char*)(g_wq + (size_t)v0 * HH);
    const char* hqb = (const char*)g_hq32[(t + 1) & 31];

    const int ar0 = tid >> 3, ac = tid & 7;
    uint32_t dA0 = SWZ(ar0 * 128 + ac * 16);
    uint32_t dA1 = SWZ((ar0 + 64) * 128 + ac * 16);
    const int brow = (tid & 255) >> 3, bc = tid & 7;
    const uint32_t dB = 16384u + SWZ(brow * 128 + bc * 16);
    const bool bldr = tid < 256;

    #define LISSUE(st, ch) do { \
        uint32_t base = sb + (st) * STAGE; \
        cpa16(base + dA0, wbase + (size_t)ar0 * HH + (ch) * 128 + ac * 16); \
        cpa16(base + dA1, wbase + (size_t)(ar0 + 64) * HH + (ch) * 128 + ac * 16); \
        if (bldr) cpa16(base + dB, hqb + (size_t)brow * HH + (ch) * 128 + bc * 16); \
        CPA_COMMIT(); \
    } while (0)

    LISSUE(0, 0);
    LISSUE(1, 1);

    int c[16];
    #pragma unroll
    for (int i = 0; i < 16; i++) c[i] = 0;

    const int lr = lane & 15, lcs = (lane >> 4) << 3;
    const int bn = (lane & 7) + ((lane >> 4) << 3);
    const int bko = ((lane >> 3) & 1) << 3;

    for (int ch = 0; ch < LCH; ch++) {
        if (ch == LCH - 1) CPA_WAIT0(); else CPA_WAIT1();
        __syncthreads();
        if (ch < LCH - 2) LISSUE((ch + 2) % 3, ch + 2);
        uint32_t sA = sb + (ch % 3) * STAGE;
        uint32_t sB = sA + 16384u;
        #pragma unroll
        for (int s4 = 0; s4 < 2; s4++) {
            int ss = kh * 2 + s4;
            uint32_t a[4], b01[4], b23[4];
            ldm_x4(a,   sA + SWZ((g * 16 + lr) * 128 + (ss * 16 + lcs) * 2));
            ldm_x4(b01, sB + SWZ(bn * 128 + (ss * 16 + bko) * 2));
            ldm_x4(b23, sB + SWZ((bn + 16) * 128 + (ss * 16 + bko) * 2));
            imma16832(c + 0,  a, b01 + 0);
            imma16832(c + 4,  a, b01 + 2);
            imma16832(c + 8,  a, b23 + 0);
            imma16832(c + 12, a, b23 + 2);
        }
    }
    #undef LISSUE

    {
        int* sp = (int*)(sbuf + SP_OFF);
        __syncthreads();
        if (kh == 1) {
            #pragma unroll
            for (int i = 0; i < 16; i++) sp[(g * 32 + lane) * 17 + i] = c[i];
        }
        __syncthreads();
        if (kh == 0) {
            #pragma unroll
            for (int i = 0; i < 16; i++) c[i] += sp[(g * 32 + lane) * 17 + i];
        }
    }
    __syncthreads();

    float* sl = (float*)sbuf;   // [128][33]
    if (kh == 0) {
        int r0 = g * 16 + (lane >> 2);
        float f0 = g_fsw[v0 + r0],     bb0 = b_out[v0 + r0];
        float f1 = g_fsw[v0 + r0 + 8], bb1 = b_out[v0 + r0 + 8];
        #pragma unroll
        for (int gg = 0; gg < 4; gg++) {
            int col = gg * 8 + 2 * (lane & 3);
            sl[r0 * 33 + col]           = f0 * (float)c[gg * 4 + 0] + bb0;
            sl[r0 * 33 + col + 1]       = f0 * (float)c[gg * 4 + 1] + bb0;
            sl[(r0 + 8) * 33 + col]     = f1 * (float)c[gg * 4 + 2] + bb1;
            sl[(r0 + 8) * 33 + col + 1] = f1 * (float)c[gg * 4 + 3] + bb1;
        }
    }
    __syncthreads();

    if (tid < 128) {
        int q = tid >> 5, b = tid & 31;
        float M = -1e30f, S = 0.f;
        #pragma unroll
        for (int r = 0; r < 32; r++) {
            float l = sl[(q * 32 + r) * 33 + b];
            if (l > M) { S = S * expf(M - l) + 1.f; M = l; }
            else       { S += expf(l - M); }
        }
        redM[q][b] = M; redS[q][b] = S;
    }
    __syncthreads();
    if (tid < 32) {
        float M = -1e30f, S = 0.f;
        #pragma unroll
        for (int q = 0; q < 4; q++) {
            float m2 = redM[q][tid], s2 = redS[q][tid];
            if (m2 > M) { S = S * expf(M - m2) + s2; M = m2; }
            else        { S += s2 * expf(m2 - M); }
        }
        g_part[t & 15][it * BB + tid] = make_float2(M, S);
    }
    __syncthreads();
}

// ---------------- merge ----------------
__device__ void merge_dev(const int* __restrict__ indices, const float* __restrict__ W_out,
                          const float* __restrict__ b_out, int tau, float* nll) {
    const int tid = threadIdx.x;
    const int wid = tid >> 5, l = tid & 31;
    const float2* part = g_part[tau & 15];
    const float* hfp = g_h32[(tau + 1) & 31];

    for (int b = wid; b < 32; b += 16) {
        float M = -1e30f;
        for (int c = l; c < NCHUNK; c += 32) M = fmaxf(M, part[c * BB + b].x);
        #pragma unroll
        for (int o = 16; o; o >>= 1) M = fmaxf(M, __shfl_xor_sync(0xFFFFFFFFu, M, o));
        float S = 0.f;
        for (int c = l; c < NCHUNK; c += 32) {
            float2 p = part[c * BB + b];
            S += p.y * expf(p.x - M);
        }
        #pragma unroll
        for (int o = 16; o; o >>= 1) S += __shfl_xor_sync(0xFFFFFFFFu, S, o);
        int tgt = indices[(tau + 1) * BB + b];
        float z = 0.f;
        for (int e = l; e < HH; e += 32) z += hfp[e * BB + b] * W_out[(size_t)tgt * HH + e];
        #pragma unroll
        for (int o = 16; o; o >>= 1) z += __shfl_xor_sync(0xFFFFFFFFu, z, o);
        if (l == 0) nll[b] = (tgt != 0) ? (logf(S) + M - (z + b_out[tgt])) : 0.f;
    }
    __syncthreads();
    if (tid == 0) {
        float acc = g_loss;
        #pragma unroll
        for (int b = 0; b < 32; b++) acc += nll[b];
        g_loss = acc;
    }
    __syncthreads();
}

// ---------------- 8-steps-per-launch kernel ----------------
// Launch k (k = -1..16):
//  CTAs 0-249:   logits(8k+p), p=0..7
//  CTAs 250-281: gates chain s = 8k+8+p (h(s)->h(s+1)), 32-CTA spin barrier per step
//  CTA 282:      merge(8k-8+p)
// All 283 CTAs co-resident (launch_bounds 512,2 -> 296 slots).
__global__ void __launch_bounds__(512, 2) k_step(const int* __restrict__ indices,
                                                 const float* __restrict__ W_out,
                                                 const float* __restrict__ b_out, int k) {
    extern __shared__ char sbuf[];
    __shared__ float redM[4][32], redS[4][32];
    __shared__ float nll[32];
    int bid = blockIdx.x;
    if (bid < NCHUNK) {
        #pragma unroll 1
        for (int p = 0; p < BDIM; p++) {
            int t = BDIM * k + p;
            if (t >= 0 && t <= TT - 2) logits_dev(b_out, t, bid, sbuf, redM, redS);
        }
    } else if (bid < NCHUNK + 32) {
        int jj = bid - NCHUNK;
        #pragma unroll 1
        for (int p = 0; p < BDIM; p++) {
            int s = BDIM * k + BDIM + p;
            if (s >= 0 && s <= TT - 2) {
                gates_dev(s, jj, sbuf);
                __threadfence();
                __syncthreads();
                if (threadIdx.x == 0) {
                    atomicAdd(&g_gcnt[s], 1u);
                    while (*(volatile unsigned*)&g_gcnt[s] < 32u) { }
                }
                __syncthreads();
            }
        }
    } else {
        #pragma unroll 1
        for (int p = 0; p < BDIM; p++) {
            int tau = BDIM * k - BDIM + p;
            if (tau >= 0 && tau <= TT - 2) merge_dev(indices, W_out, b_out, tau, nll);
        }
    }
}

__global__ void k_out(float* out, int n) {
    int i = blockIdx.x * blockDim.x + threadIdx.x;
    if (i < n) out[i] = (i == 0) ? g_loss : 0.f;
}

// ---------------- launch ----------------
extern "C" void kernel_launch(void* const* d_in, const int* in_sizes, int n_in,
                              void* d_out, int out_size) {
    const int*   indices = (const int*)d_in[0];
    const float* emb     = (const float*)d_in[1];
    const float* W_ih    = (const float*)d_in[2];
    const float* W_hh    = (const float*)d_in[3];
    const float* b_ih    = (const float*)d_in[4];
    const float* b_hh    = (const float*)d_in[5];
    const float* W_out   = (const float*)d_in[6];
    const float* b_out   = (const float*)d_in[7];
    const float* h0      = (const float*)d_in[8];
    const float* c0      = (const float*)d_in[9];

    cudaFuncSetAttribute(k_step, cudaFuncAttributeMaxDynamicSharedMemorySize, SMEM_SZ);

    k_setup1<<<VV / 8, 256>>>(W_out, emb);
    k_setup2<<<GG / 8, 256>>>(W_ih, W_hh, b_ih, b_hh);
    k_setup3<<<508 + 128, 256>>>(indices, emb, h0, c0);

    // k=-1: gates-only warmup (h1..h8). k=0..15: 8 steps each. k=16: trailing merges.
    for (int k = -1; k <= 16; k++)
        k_step<<<NCHUNK + 32 + 1, 512, SMEM_SZ>>>(indices, W_out, b_out, k);
    k_out<<<(out_size + 255) / 256, 256>>>((float*)d_out, out_size);
}

// round 15
// speedup vs baseline: 1.0371x; 1.0371x over previous
#include <cuda_runtime.h>
#include <cuda_bf16.h>
#include <stdint.h>
#include <stddef.h>
#include <math.h>

#define TT 128
#define BB 32
#define VV 32000
#define EE 512
#define HH 1024
#define KK 1536
#define GG 4096
#define NCHUNK 250       // logits chunks of 128 vocab rows
#define STAGE 20480      // stage bytes: A 16K + B 4K
#define LCH 8            // logits K-chunks of 128 int8
#define GCH 12           // gates K-chunks of 128 int8
#define SP_OFF 24576     // int partial buffer offset in sbuf
#define SMEM_SZ (3 * STAGE)
#define NG 43            // gates CTAs (42 x 96 rows + 1 x 64)
#define GRID (NCHUNK + NG + 1)

// ---------------- scratch ----------------
__device__ __align__(16) float g_h16[16][HH * BB];         // h fp32 [k][b], ring
__device__ __align__(16) signed char g_hq16[16][BB * HH];  // h int8 [b][k], ring
__device__ __align__(16) float g_c[HH * BB];               // c[k][b]
__device__ __align__(16) signed char g_wq[(size_t)VV * HH];
__device__ __align__(16) float g_fsw[VV];
__device__ __align__(16) signed char g_wqg[(size_t)GG * KK];
__device__ __align__(16) float g_sg[GG];
__device__ __align__(16) float g_biasp[GG];
__device__ __align__(16) signed char g_xq[(TT - 1) * BB * EE];
__device__ unsigned g_xmax = 0u;
__device__ float2 g_part[8][NCHUNK * BB];                  // ring by t&7
__device__ float g_loss;
__device__ unsigned g_gcnt[160];                           // per-step gates barrier counters

// permuted-row decode: id (0..4095) -> tile j, row r, units U, first unit u0
__device__ __host__ __forceinline__ void gdecode(int id, int& j, int& r, int& U, int& u0) {
    if (id < 4032) { j = id / 96; r = id % 96; U = 24; u0 = 24 * j; }
    else           { j = 42; r = id - 4032; U = 16; u0 = 1008; }
}

// ---------------- helpers ----------------
__device__ __forceinline__ uint32_t su32(const void* p) {
    uint32_t a;
    asm("{ .reg .u64 t; cvta.to.shared.u64 t, %1; cvt.u32.u64 %0, t; }" : "=r"(a) : "l"(p));
    return a;
}
#define SWZ(o) ((o) ^ (((o) >> 3) & 0x70))

__device__ __forceinline__ void ldm_x4(uint32_t* r, uint32_t addr) {
    asm volatile("ldmatrix.sync.aligned.m8n8.x4.shared.b16 {%0,%1,%2,%3}, [%4];"
                 : "=r"(r[0]), "=r"(r[1]), "=r"(r[2]), "=r"(r[3]) : "r"(addr));
}
__device__ __forceinline__ void imma16832(int* c, const uint32_t* a, const uint32_t* b) {
    asm volatile("mma.sync.aligned.m16n8k32.row.col.s32.s8.s8.s32 "
                 "{%0,%1,%2,%3}, {%4,%5,%6,%7}, {%8,%9}, {%0,%1,%2,%3};"
                 : "+r"(c[0]), "+r"(c[1]), "+r"(c[2]), "+r"(c[3])
                 : "r"(a[0]), "r"(a[1]), "r"(a[2]), "r"(a[3]), "r"(b[0]), "r"(b[1]));
}
__device__ __forceinline__ void cpa16(uint32_t dst, const void* src) {
    asm volatile("cp.async.cg.shared.global [%0], [%1], 16;" :: "r"(dst), "l"(src) : "memory");
}
#define CPA_COMMIT() asm volatile("cp.async.commit_group;" ::: "memory")
#define CPA_WAIT1()  asm volatile("cp.async.wait_group 1;" ::: "memory")
#define CPA_WAIT0()  asm volatile("cp.async.wait_group 0;" ::: "memory")

__device__ __forceinline__ signed char q8(float v) {
    int x = __float2int_rn(v);
    x = x > 127 ? 127 : (x < -127 ? -127 : x);
    return (signed char)x;
}

// ---------------- setup kernels ----------------
__global__ void k_setup1(const float* __restrict__ W, const float* __restrict__ emb) {
    int wid = blockIdx.x * 8 + (threadIdx.x >> 5);
    int lane = threadIdx.x & 31;
    const float* row = W + (size_t)wid * HH;
    float m = 0.f;
    #pragma unroll
    for (int i = 0; i < 32; i++) m = fmaxf(m, fabsf(row[lane + 32 * i]));
    #pragma unroll
    for (int o = 16; o; o >>= 1) m = fmaxf(m, __shfl_xor_sync(0xFFFFFFFFu, m, o));
    float inv = (m > 1e-30f) ? 127.f / m : 0.f;
    if (lane == 0) g_fsw[wid] = m / (127.f * 127.f);
    signed char* dst = g_wq + (size_t)wid * HH;
    #pragma unroll
    for (int i = 0; i < 32; i++) {
        int k = lane + 32 * i;
        dst[k] = q8(row[k] * inv);
    }
    size_t gtid = (size_t)blockIdx.x * blockDim.x + threadIdx.x;
    size_t n = (size_t)VV * EE, nt = (size_t)gridDim.x * blockDim.x;
    float em = 0.f;
    for (size_t i = gtid; i < n; i += nt) em = fmaxf(em, emb[i]);
    #pragma unroll
    for (int o = 16; o; o >>= 1) em = fmaxf(em, __shfl_xor_sync(0xFFFFFFFFu, em, o));
    if (lane == 0 && em > 0.f) atomicMax(&g_xmax, __float_as_uint(em));
}

__global__ void k_setup2(const float* __restrict__ W_ih, const float* __restrict__ W_hh,
                         const float* __restrict__ b_ih, const float* __restrict__ b_hh) {
    int id = blockIdx.x * 8 + (threadIdx.x >> 5);
    int lane = threadIdx.x & 31;
    int j, r, U, u0;
    gdecode(id, j, r, U, u0);
    int srcrow = (r / U) * HH + u0 + (r % U);
    float s_x = __uint_as_float(g_xmax) / 127.f;
    const float sh = 1.f / 127.f;
    float m = 0.f;
    #pragma unroll
    for (int i = 0; i < 48; i++) {
        int k = lane + 32 * i;
        float w = (k < EE) ? W_ih[(size_t)srcrow * EE + k] * s_x
                           : W_hh[(size_t)srcrow * HH + (k - EE)] * sh;
        m = fmaxf(m, fabsf(w));
    }
    #pragma unroll
    for (int o = 16; o; o >>= 1) m = fmaxf(m, __shfl_xor_sync(0xFFFFFFFFu, m, o));
    float inv = (m > 1e-30f) ? 127.f / m : 0.f;
    if (lane == 0) { g_sg[id] = m / 127.f; g_biasp[id] = b_ih[srcrow] + b_hh[srcrow]; }
    signed char* dst = g_wqg + (size_t)id * KK;
    #pragma unroll
    for (int i = 0; i < 48; i++) {
        int k = lane + 32 * i;
        float w = (k < EE) ? W_ih[(size_t)srcrow * EE + k] * s_x
                           : W_hh[(size_t)srcrow * HH + (k - EE)] * sh;
        dst[k] = q8(w * inv);
    }
}

__global__ void k_setup3(const int* __restrict__ indices, const float* __restrict__ emb,
                         const float* __restrict__ h0, const float* __restrict__ c0) {
    if (blockIdx.x < 508) {
        int tb = blockIdx.x * 8 + (threadIdx.x >> 5);
        int lane = threadIdx.x & 31;
        if (tb < (TT - 1) * BB) {
            int idx = indices[tb];
            float inv = 127.f / __uint_as_float(g_xmax);
            const float* e = emb + (size_t)idx * EE;
            signed char* dst = g_xq + (size_t)tb * EE;
            #pragma unroll
            for (int i = 0; i < 16; i++) {
                int k = lane + 32 * i;
                dst[k] = q8(fmaxf(e[k], 0.f) * inv);
            }
        }
    } else {
        int i = (blockIdx.x - 508) * 256 + threadIdx.x;
        if (i < HH * BB) {
            int b = i / HH, k = i % HH;
            g_h16[0][k * BB + b] = h0[i];
            g_c[k * BB + b] = c0[i];
            g_hq16[0][i] = q8(h0[i] * 127.f);
        }
        if (blockIdx.x == 508) {
            if (threadIdx.x < 160) g_gcnt[threadIdx.x] = 0u;
            if (threadIdx.x == 160) g_loss = 0.f;
        }
    }
}

// ---------------- gates (16 warps, K-split x2) + LSTM, variable tile ----------------
// tile jj: R rows (96 or 64), U = R/4 hidden units starting at u0, base = permuted row base.
__device__ void gates_dev(int s, int jj, char* sbuf) {
    const int tid = threadIdx.x;
    const int w = tid >> 5, lane = tid & 31;
    const int g = w >> 1, kh = w & 1;
    int R, U, u0, base;
    if (jj < 42) { R = 96; U = 24; u0 = 24 * jj; base = 96 * jj; }
    else         { R = 64; U = 16; u0 = 1008;   base = 4032; }
    const int G = R >> 4;
    const uint32_t sb = su32(sbuf);
    const char* xqb = (const char*)(g_xq + (size_t)s * BB * EE);
    const char* hqb = (const char*)g_hq16[s & 15];
    const int out = (s + 1) & 15;
    const char* wbase = (const char*)(g_wqg + (size_t)base * KK);

    const int ar0 = tid >> 3, ac = tid & 7;
    const int ar1 = ar0 + 64;
    uint32_t dA0 = SWZ(ar0 * 128 + ac * 16);
    uint32_t dA1 = SWZ(ar1 * 128 + ac * 16);
    const bool a1ok = (ar1 < R);
    const int brow = (tid & 255) >> 3, bc = tid & 7;
    const uint32_t dB = 16384u + SWZ(brow * 128 + bc * 16);
    const bool bldr = tid < 256;

    #define GISSUE(st, ch) do { \
        uint32_t base2 = sb + (st) * STAGE; \
        cpa16(base2 + dA0, wbase + (size_t)ar0 * KK + (ch) * 128 + ac * 16); \
        if (a1ok) cpa16(base2 + dA1, wbase + (size_t)ar1 * KK + (ch) * 128 + ac * 16); \
        if (bldr) { \
            const char* bp = ((ch) < 4) ? (xqb + (size_t)brow * EE + (ch) * 128 + bc * 16) \
                                        : (hqb + (size_t)brow * HH + ((ch) - 4) * 128 + bc * 16); \
            cpa16(base2 + dB, bp); \
        } \
        CPA_COMMIT(); \
    } while (0)

    GISSUE(0, 0);
    GISSUE(1, 1);

    int c[16];
    #pragma unroll
    for (int i = 0; i < 16; i++) c[i] = 0;

    const int lr = lane & 15, lcs = (lane >> 4) << 3;
    const int bn = (lane & 7) + ((lane >> 4) << 3);
    const int bko = ((lane >> 3) & 1) << 3;

    for (int ch = 0; ch < GCH; ch++) {
        if (ch == GCH - 1) CPA_WAIT0(); else CPA_WAIT1();
        __syncthreads();
        if (ch < GCH - 2) GISSUE((ch + 2) % 3, ch + 2);
        if (g < G) {
            uint32_t sA = sb + (ch % 3) * STAGE;
            uint32_t sB = sA + 16384u;
            #pragma unroll
            for (int s4 = 0; s4 < 2; s4++) {
                int ss = kh * 2 + s4;
                uint32_t a[4], b01[4], b23[4];
                ldm_x4(a,   sA + SWZ((g * 16 + lr) * 128 + (ss * 16 + lcs) * 2));
                ldm_x4(b01, sB + SWZ(bn * 128 + (ss * 16 + bko) * 2));
                ldm_x4(b23, sB + SWZ((bn + 16) * 128 + (ss * 16 + bko) * 2));
                imma16832(c + 0,  a, b01 + 0);
                imma16832(c + 4,  a, b01 + 2);
                imma16832(c + 8,  a, b23 + 0);
                imma16832(c + 12, a, b23 + 2);
            }
        }
    }
    #undef GISSUE

    {
        int* sp = (int*)(sbuf + SP_OFF);
        __syncthreads();
        if (kh == 1 && g < G) {
            #pragma unroll
            for (int i = 0; i < 16; i++) sp[(g * 32 + lane) * 17 + i] = c[i];
        }
        __syncthreads();
        if (kh == 0 && g < G) {
            #pragma unroll
            for (int i = 0; i < 16; i++) c[i] += sp[(g * 32 + lane) * 17 + i];
        }
    }
    __syncthreads();

    float* sl = (float*)sbuf;   // [R][33]
    if (kh == 0 && g < G) {
        int r0 = g * 16 + (lane >> 2);
        float s0 = g_sg[base + r0],     bb0 = g_biasp[base + r0];
        float s1 = g_sg[base + r0 + 8], bb1 = g_biasp[base + r0 + 8];
        #pragma unroll
        for (int gg = 0; gg < 4; gg++) {
            int col = gg * 8 + 2 * (lane & 3);
            sl[r0 * 33 + col]           = s0 * (float)c[gg * 4 + 0] + bb0;
            sl[r0 * 33 + col + 1]       = s0 * (float)c[gg * 4 + 1] + bb0;
            sl[(r0 + 8) * 33 + col]     = s1 * (float)c[gg * 4 + 2] + bb1;
            sl[(r0 + 8) * 33 + col + 1] = s1 * (float)c[gg * 4 + 3] + bb1;
        }
    }
    __syncthreads();
    {
        int hu = tid >> 4;
        int b0 = (tid & 15) * 2;
        if (hu < U) {
            int k = u0 + hu;
            #pragma unroll
            for (int q = 0; q < 2; q++) {
                int b = b0 + q;
                float ig = sl[hu * 33 + b];
                float fg = sl[(U + hu) * 33 + b];
                float gg = sl[(2 * U + hu) * 33 + b];
                float og = sl[(3 * U + hu) * 33 + b];
                float si = 1.f / (1.f + expf(-ig));
                float sf = 1.f / (1.f + expf(-fg));
                float so = 1.f / (1.f + expf(-og));
                float cn = sf * g_c[k * BB + b] + si * tanhf(gg);
                g_c[k * BB + b] = cn;
                float h = so * tanhf(cn);
                g_h16[(s + 1) & 15][k * BB + b] = h;
                g_hq16[out][b * HH + k] = q8(h * 127.f);
            }
        }
    }
}

// ---------------- logits (16 warps: 8 rowgrp x 2 K-split) ----------------
__device__ void logits_dev(const float* __restrict__ b_out, int t, int it, char* sbuf,
                           float (*redM)[32], float (*redS)[32]) {
    const int tid = threadIdx.x;
    const int w = tid >> 5, lane = tid & 31;
    const int g = w >> 1, kh = w & 1;
    const int v0 = it * 128;
    const uint32_t sb = su32(sbuf);
    const char* wbase = (const char*)(g_wq + (size_t)v0 * HH);
    const char* hqb = (const char*)g_hq16[(t + 1) & 15];

    const int ar0 = tid >> 3, ac = tid & 7;
    uint32_t dA0 = SWZ(ar0 * 128 + ac * 16);
    uint32_t dA1 = SWZ((ar0 + 64) * 128 + ac * 16);
    const int brow = (tid & 255) >> 3, bc = tid & 7;
    const uint32_t dB = 16384u + SWZ(brow * 128 + bc * 16);
    const bool bldr = tid < 256;

    #define LISSUE(st, ch) do { \
        uint32_t base = sb + (st) * STAGE; \
        cpa16(base + dA0, wbase + (size_t)ar0 * HH + (ch) * 128 + ac * 16); \
        cpa16(base + dA1, wbase + (size_t)(ar0 + 64) * HH + (ch) * 128 + ac * 16); \
        if (bldr) cpa16(base + dB, hqb + (size_t)brow * HH + (ch) * 128 + bc * 16); \
        CPA_COMMIT(); \
    } while (0)

    LISSUE(0, 0);
    LISSUE(1, 1);

    int c[16];
    #pragma unroll
    for (int i = 0; i < 16; i++) c[i] = 0;

    const int lr = lane & 15, lcs = (lane >> 4) << 3;
    const int bn = (lane & 7) + ((lane >> 4) << 3);
    const int bko = ((lane >> 3) & 1) << 3;

    for (int ch = 0; ch < LCH; ch++) {
        if (ch == LCH - 1) CPA_WAIT0(); else CPA_WAIT1();
        __syncthreads();
        if (ch < LCH - 2) LISSUE((ch + 2) % 3, ch + 2);
        uint32_t sA = sb + (ch % 3) * STAGE;
        uint32_t sB = sA + 16384u;
        #pragma unroll
        for (int s4 = 0; s4 < 2; s4++) {
            int ss = kh * 2 + s4;
            uint32_t a[4], b01[4], b23[4];
            ldm_x4(a,   sA + SWZ((g * 16 + lr) * 128 + (ss * 16 + lcs) * 2));
            ldm_x4(b01, sB + SWZ(bn * 128 + (ss * 16 + bko) * 2));
            ldm_x4(b23, sB + SWZ((bn + 16) * 128 + (ss * 16 + bko) * 2));
            imma16832(c + 0,  a, b01 + 0);
            imma16832(c + 4,  a, b01 + 2);
            imma16832(c + 8,  a, b23 + 0);
            imma16832(c + 12, a, b23 + 2);
        }
    }
    #undef LISSUE

    {
        int* sp = (int*)(sbuf + SP_OFF);
        __syncthreads();
        if (kh == 1) {
            #pragma unroll
            for (int i = 0; i < 16; i++) sp[(g * 32 + lane) * 17 + i] = c[i];
        }
        __syncthreads();
        if (kh == 0) {
            #pragma unroll
            for (int i = 0; i < 16; i++) c[i] += sp[(g * 32 + lane) * 17 + i];
        }
    }
    __syncthreads();

    float* sl = (float*)sbuf;   // [128][33]
    if (kh == 0) {
        int r0 = g * 16 + (lane >> 2);
        float f0 = g_fsw[v0 + r0],     bb0 = b_out[v0 + r0];
        float f1 = g_fsw[v0 + r0 + 8], bb1 = b_out[v0 + r0 + 8];
        #pragma unroll
        for (int gg = 0; gg < 4; gg++) {
            int col = gg * 8 + 2 * (lane & 3);
            sl[r0 * 33 + col]           = f0 * (float)c[gg * 4 + 0] + bb0;
            sl[r0 * 33 + col + 1]       = f0 * (float)c[gg * 4 + 1] + bb0;
            sl[(r0 + 8) * 33 + col]     = f1 * (float)c[gg * 4 + 2] + bb1;
            sl[(r0 + 8) * 33 + col + 1] = f1 * (float)c[gg * 4 + 3] + bb1;
        }
    }
    __syncthreads();

    if (tid < 128) {
        int q = tid >> 5, b = tid & 31;
        float M = -1e30f, S = 0.f;
        #pragma unroll
        for (int r = 0; r < 32; r++) {
            float l = sl[(q * 32 + r) * 33 + b];
            if (l > M) { S = S * expf(M - l) + 1.f; M = l; }
            else       { S += expf(l - M); }
        }
        redM[q][b] = M; redS[q][b] = S;
    }
    __syncthreads();
    if (tid < 32) {
        float M = -1e30f, S = 0.f;
        #pragma unroll
        for (int q = 0; q < 4; q++) {
            float m2 = redM[q][tid], s2 = redS[q][tid];
            if (m2 > M) { S = S * expf(M - m2) + s2; M = m2; }
            else        { S += s2 * expf(m2 - M); }
        }
        g_part[t & 7][it * BB + tid] = make_float2(M, S);
    }
    __syncthreads();
}

// ---------------- merge ----------------
__device__ void merge_dev(const int* __restrict__ indices, const float* __restrict__ W_out,
                          const float* __restrict__ b_out, int tau, float* nll) {
    const int tid = threadIdx.x;
    const int wid = tid >> 5, l = tid & 31;
    const float2* part = g_part[tau & 7];
    const float* hfp = g_h16[(tau + 1) & 15];

    for (int b = wid; b < 32; b += 16) {
        float M = -1e30f;
        for (int c = l; c < NCHUNK; c += 32) M = fmaxf(M, part[c * BB + b].x);
        #pragma unroll
        for (int o = 16; o; o >>= 1) M = fmaxf(M, __shfl_xor_sync(0xFFFFFFFFu, M, o));
        float S = 0.f;
        for (int c = l; c < NCHUNK; c += 32) {
            float2 p = part[c * BB + b];
            S += p.y * expf(p.x - M);
        }
        #pragma unroll
        for (int o = 16; o; o >>= 1) S += __shfl_xor_sync(0xFFFFFFFFu, S, o);
        int tgt = indices[(tau + 1) * BB + b];
        float z = 0.f;
        for (int e = l; e < HH; e += 32) z += hfp[e * BB + b] * W_out[(size_t)tgt * HH + e];
        #pragma unroll
        for (int o = 16; o; o >>= 1) z += __shfl_xor_sync(0xFFFFFFFFu, z, o);
        if (l == 0) nll[b] = (tgt != 0) ? (logf(S) + M - (z + b_out[tgt])) : 0.f;
    }
    __syncthreads();
    if (tid == 0) {
        float acc = g_loss;
        #pragma unroll
        for (int b = 0; b < 32; b++) acc += nll[b];
        g_loss = acc;
    }
    __syncthreads();
}

// ---------------- 4-steps-per-launch kernel ----------------
// Launch k (k = -1..32):
//  CTAs 0-249:   logits(4k+p), p=0..3
//  CTAs 250-292: gates chain s = 4k+4+p (h(s)->h(s+1)), 43-CTA spin barrier per step
//  CTA 293:      merge(4k-4+p)
// All 294 CTAs co-resident (launch_bounds 512,2 -> 296 slots).
__global__ void __launch_bounds__(512, 2) k_step(const int* __restrict__ indices,
                                                 const float* __restrict__ W_out,
                                                 const float* __restrict__ b_out, int k) {
    extern __shared__ char sbuf[];
    __shared__ float redM[4][32], redS[4][32];
    __shared__ float nll[32];
    int bid = blockIdx.x;
    if (bid < NCHUNK) {
        #pragma unroll 1
        for (int p = 0; p < 4; p++) {
            int t = 4 * k + p;
            if (t >= 0 && t <= TT - 2) logits_dev(b_out, t, bid, sbuf, redM, redS);
        }
    } else if (bid < NCHUNK + NG) {
        int jj = bid - NCHUNK;
        #pragma unroll 1
        for (int p = 0; p < 4; p++) {
            int s = 4 * k + 4 + p;
            if (s >= 0 && s <= TT - 2) {
                gates_dev(s, jj, sbuf);
                __threadfence();
                __syncthreads();
                if (threadIdx.x == 0) {
                    atomicAdd(&g_gcnt[s], 1u);
                    while (*(volatile unsigned*)&g_gcnt[s] < (unsigned)NG) { }
                }
                __syncthreads();
            }
        }
    } else {
        #pragma unroll 1
        for (int p = 0; p < 4; p++) {
            int tau = 4 * k - 4 + p;
            if (tau >= 0 && tau <= TT - 2) merge_dev(indices, W_out, b_out, tau, nll);
        }
    }
}

__global__ void k_out(float* out, int n) {
    int i = blockIdx.x * blockDim.x + threadIdx.x;
    if (i < n) out[i] = (i == 0) ? g_loss : 0.f;
}

// ---------------- launch ----------------
extern "C" void kernel_launch(void* const* d_in, const int* in_sizes, int n_in,
                              void* d_out, int out_size) {
    const int*   indices = (const int*)d_in[0];
    const float* emb     = (const float*)d_in[1];
    const float* W_ih    = (const float*)d_in[2];
    const float* W_hh    = (const float*)d_in[3];
    const float* b_ih    = (const float*)d_in[4];
    const float* b_hh    = (const float*)d_in[5];
    const float* W_out   = (const float*)d_in[6];
    const float* b_out   = (const float*)d_in[7];
    const float* h0      = (const float*)d_in[8];
    const float* c0      = (const float*)d_in[9];

    cudaFuncSetAttribute(k_step, cudaFuncAttributeMaxDynamicSharedMemorySize, SMEM_SZ);

    k_setup1<<<VV / 8, 256>>>(W_out, emb);
    k_setup2<<<GG / 8, 256>>>(W_ih, W_hh, b_ih, b_hh);
    k_setup3<<<508 + 128, 256>>>(indices, emb, h0, c0);

    // k=-1: gates-only warmup (h1..h4). k=0..31: 4 steps each. k=32: trailing merges.
    for (int k = -1; k <= 32; k++)
        k_step<<<GRID, 512, SMEM_SZ>>>(indices, W_out, b_out, k);
    k_out<<<(out_size + 255) / 256, 256>>>((float*)d_out, out_size);
}